// round 3
// baseline (speedup 1.0000x reference)
#include <cuda_runtime.h>
#include <cuda_bf16.h>
#include <cstdint>
#include <math.h>

#define B_  64
#define T_  2048
#define D_  1024
#define H1_ 512

// ---------------- device scratch (static, no allocation) ----------------
__device__ float         g_weff[H1_];
__device__ float         g_beff;
__device__ __nv_bfloat16 g_w1t[H1_ * D_];   // [H1][D], k-contiguous
__device__ float         g_logits[B_ * T_];

// ---------------- smem geometry ----------------
#define XS_STRIDE 1032                 // 1024 + 8 pad (bf16 elems) -> conflict-free frag reads
#define WS_STRIDE 72                   // 64 + 8 pad
#define XS_ELEMS  (64 * XS_STRIDE)     // 66048 bf16 = 132096 B
#define WS_ELEMS  (128 * WS_STRIDE)    // 9216 bf16  = 18432 B per buffer
#define SMEM_BYTES (XS_ELEMS*2 + 2*WS_ELEMS*2 + 2*H1_*4 + 128*4)  // 173568

// ---------------- ptx helpers ----------------
__device__ __forceinline__ uint32_t smem_u32(const void* p) {
    return (uint32_t)__cvta_generic_to_shared(p);
}
__device__ __forceinline__ void cp_async16(uint32_t dst, const void* src) {
    asm volatile("cp.async.cg.shared.global [%0], [%1], 16;\n" :: "r"(dst), "l"(src));
}
__device__ __forceinline__ void cp_commit() { asm volatile("cp.async.commit_group;\n"); }
template<int N> __device__ __forceinline__ void cp_wait() {
    asm volatile("cp.async.wait_group %0;\n" :: "n"(N));
}
__device__ __forceinline__ void mma_16816(float c[4],
                                          uint32_t a0, uint32_t a1, uint32_t a2, uint32_t a3,
                                          uint32_t b0, uint32_t b1) {
    asm volatile(
        "mma.sync.aligned.m16n8k16.row.col.f32.bf16.bf16.f32 "
        "{%0,%1,%2,%3}, {%4,%5,%6,%7}, {%8,%9}, {%0,%1,%2,%3};\n"
        : "+f"(c[0]), "+f"(c[1]), "+f"(c[2]), "+f"(c[3])
        : "r"(a0), "r"(a1), "r"(a2), "r"(a3), "r"(b0), "r"(b1));
}

// ---------------- prep kernels ----------------
__global__ void prep_weff_kernel(const float* __restrict__ W2, const float* __restrict__ b2,
                                 const float* __restrict__ W3, const float* __restrict__ b3) {
    int h = threadIdx.x;                    // 512 threads
    float s = 0.f;
    #pragma unroll
    for (int j = 0; j < 32; j++) s += W2[h * 32 + j] * W3[j];
    g_weff[h] = s;
    if (h == 0) {
        float t = 0.f;
        #pragma unroll
        for (int j = 0; j < 32; j++) t += b2[j] * W3[j];
        g_beff = t + *b3;
    }
}

// W1 is [D][H1] row-major; build bf16 transpose [H1][D] with coalesced writes.
__global__ void prep_w1t_kernel(const float* __restrict__ W1) {
    int idx = blockIdx.x * 256 + threadIdx.x;     // 0 .. H1*D-1
    int h = idx >> 10;                            // /1024
    int d = idx & 1023;
    g_w1t[idx] = __float2bfloat16(W1[d * H1_ + h]);
}

// ---------------- main fused kernel ----------------
// grid (T/64, B), block 256. CTA: 64 tokens x full H1 (4 n-chunks of 128).
__global__ void __launch_bounds__(256, 1)
fused_mlp_kernel(const float* __restrict__ X, const int* __restrict__ seq_len,
                 const float* __restrict__ b1) {
    extern __shared__ char smem_raw[];
    __nv_bfloat16* Xs     = (__nv_bfloat16*)smem_raw;
    __nv_bfloat16* WsBase = Xs + XS_ELEMS;                 // 2 buffers
    float*         weff_s = (float*)(WsBase + 2 * WS_ELEMS);
    float*         b1_s   = weff_s + H1_;
    float*         tokAcc = b1_s + H1_;                    // [2][64] (by warp_n)

    const int b  = blockIdx.y;
    const int t0 = blockIdx.x * 64;
    const int sl = seq_len[b];
    if (t0 >= sl) return;                                  // masked tile: dead work

    const int tid  = threadIdx.x;
    const int lane = tid & 31;
    const int wid  = tid >> 5;
    const int wm   = wid >> 1;                             // 0..3 (token rows)
    const int wn   = wid & 1;                              // 0..1 (n halves)
    const int g4   = lane >> 2;                            // 0..7
    const int kq   = (lane & 3) * 2;

    // stage weff / b1 in smem, init accumulators
    for (int i = tid; i < H1_; i += 256) { weff_s[i] = g_weff[i]; b1_s[i] = b1[i]; }
    if (tid < 128) tokAcc[tid] = 0.f;

    // stage X tile [64 x 1024] fp32 -> bf16 smem (once)
    const float* Xb = X + ((size_t)b * T_ + t0) * D_;
    for (int i = tid; i < 64 * 256; i += 256) {            // 64 float4 per thread
        int row = i >> 8, c4 = i & 255;
        float4 v = reinterpret_cast<const float4*>(Xb + row * D_)[c4];
        __nv_bfloat162 lo = __floats2bfloat162_rn(v.x, v.y);
        __nv_bfloat162 hi = __floats2bfloat162_rn(v.z, v.w);
        uint2 pk;
        pk.x = *reinterpret_cast<uint32_t*>(&lo);
        pk.y = *reinterpret_cast<uint32_t*>(&hi);
        *reinterpret_cast<uint2*>(&Xs[row * XS_STRIDE + c4 * 4]) = pk;
    }
    __syncthreads();

    // W tile loader: [128 n x 64 k] bf16 via cp.async (4 x 16B per thread)
    auto load_w = [&](int nc, int kc, int buf) {
        const __nv_bfloat16* src = g_w1t + (size_t)(nc * 128) * D_ + kc * 64;
        __nv_bfloat16* dstb = WsBase + buf * WS_ELEMS;
        #pragma unroll
        for (int j = 0; j < 4; j++) {
            int idx = tid + j * 256;                        // 0..1023
            int row = idx >> 3, seg = idx & 7;
            cp_async16(smem_u32(&dstb[row * WS_STRIDE + seg * 8]),
                       src + row * D_ + seg * 8);
        }
        cp_commit();
    };

    const int arow = wm * 16 + g4;

    for (int nc = 0; nc < 4; nc++) {
        float c[8][4];
        #pragma unroll
        for (int nf = 0; nf < 8; nf++)
            { c[nf][0] = 0.f; c[nf][1] = 0.f; c[nf][2] = 0.f; c[nf][3] = 0.f; }

        load_w(nc, 0, 0);
        for (int kc = 0; kc < 16; kc++) {
            if (kc < 15) { load_w(nc, kc + 1, (kc + 1) & 1); cp_wait<1>(); }
            else         { cp_wait<0>(); }
            __syncthreads();

            const __nv_bfloat16* Wb = WsBase + (kc & 1) * WS_ELEMS;
            #pragma unroll
            for (int ks = 0; ks < 4; ks++) {
                const int ka = kc * 64 + ks * 16 + kq;
                uint32_t a0 = *(const uint32_t*)&Xs[arow * XS_STRIDE + ka];
                uint32_t a1 = *(const uint32_t*)&Xs[(arow + 8) * XS_STRIDE + ka];
                uint32_t a2 = *(const uint32_t*)&Xs[arow * XS_STRIDE + ka + 8];
                uint32_t a3 = *(const uint32_t*)&Xs[(arow + 8) * XS_STRIDE + ka + 8];
                const int kb = ks * 16 + kq;
                #pragma unroll
                for (int nf = 0; nf < 8; nf++) {
                    const int brow = wn * 64 + nf * 8 + g4;
                    uint32_t b0  = *(const uint32_t*)&Wb[brow * WS_STRIDE + kb];
                    uint32_t b1r = *(const uint32_t*)&Wb[brow * WS_STRIDE + kb + 8];
                    mma_16816(c[nf], a0, a1, a2, a3, b0, b1r);
                }
            }
            __syncthreads();
        }

        // epilogue: bias + relu + weighted sum over this n-chunk
        float p0 = 0.f, p1 = 0.f;
        #pragma unroll
        for (int nf = 0; nf < 8; nf++) {
            const int ng = nc * 128 + wn * 64 + nf * 8 + kq;
            float w0 = weff_s[ng], w1v = weff_s[ng + 1];
            float q0 = b1_s[ng],   q1  = b1_s[ng + 1];
            p0 += fmaxf(c[nf][0] + q0, 0.f) * w0 + fmaxf(c[nf][1] + q1, 0.f) * w1v;
            p1 += fmaxf(c[nf][2] + q0, 0.f) * w0 + fmaxf(c[nf][3] + q1, 0.f) * w1v;
        }
        p0 += __shfl_xor_sync(0xffffffffu, p0, 1);
        p0 += __shfl_xor_sync(0xffffffffu, p0, 2);
        p1 += __shfl_xor_sync(0xffffffffu, p1, 1);
        p1 += __shfl_xor_sync(0xffffffffu, p1, 2);
        if ((lane & 3) == 0) {                       // one warp per (wm, wn): no races
            int r = wm * 16 + g4;
            tokAcc[wn * 64 + r]     += p0;
            tokAcc[wn * 64 + r + 8] += p1;
        }
    }
    __syncthreads();

    if (tid < 64) {
        int t = t0 + tid;
        if (t < sl) {
            float logit = tokAcc[tid] + tokAcc[64 + tid] + g_beff;
            g_logits[b * T_ + t] = 1.f / (1.f + expf(-logit));
        }
    }
}

// ---------------- exact top-k mean per batch ----------------
// k-th largest via binary search on float bits (all values positive -> uint order).
__global__ void __launch_bounds__(256)
topk_kernel(const int* __restrict__ seq_len, float* __restrict__ out) {
    const int b  = blockIdx.x;
    const int sl = seq_len[b];
    const int k  = sl / 16 + 1;
    const int tid = threadIdx.x;

    float vals[8];
    #pragma unroll
    for (int i = 0; i < 8; i++) {
        int t = tid + i * 256;
        vals[i] = (t < sl) ? g_logits[b * T_ + t] : -1.0f;   // sentinel below range
    }

    __shared__ int   ired[8];
    __shared__ float fred[8];
    __shared__ unsigned bcast;

    unsigned lo = 0u, hi = 0x3F800000u;                      // [0, 1.0]
    while (lo < hi) {
        unsigned mid = lo + ((hi - lo + 1u) >> 1);
        float fm = __uint_as_float(mid);
        int cnt = 0;
        #pragma unroll
        for (int i = 0; i < 8; i++) cnt += (vals[i] >= fm);
        #pragma unroll
        for (int o = 16; o; o >>= 1) cnt += __shfl_xor_sync(0xffffffffu, cnt, o);
        if ((tid & 31) == 0) ired[tid >> 5] = cnt;
        __syncthreads();
        if (tid == 0) {
            int c = 0;
            #pragma unroll
            for (int w = 0; w < 8; w++) c += ired[w];
            bcast = (c >= k) ? 1u : 0u;
        }
        __syncthreads();
        if (bcast) lo = mid; else hi = mid - 1u;
    }

    const float vk = __uint_as_float(lo);                    // exact k-th largest
    float s = 0.f; int cg = 0;
    #pragma unroll
    for (int i = 0; i < 8; i++)
        if (vals[i] > vk) { s += vals[i]; cg++; }
    #pragma unroll
    for (int o = 16; o; o >>= 1) {
        s  += __shfl_xor_sync(0xffffffffu, s, o);
        cg += __shfl_xor_sync(0xffffffffu, cg, o);
    }
    if ((tid & 31) == 0) { ired[tid >> 5] = cg; fred[tid >> 5] = s; }
    __syncthreads();
    if (tid == 0) {
        float S = 0.f; int CG = 0;
        #pragma unroll
        for (int w = 0; w < 8; w++) { S += fred[w]; CG += ired[w]; }
        out[b] = (S + vk * (float)(k - CG)) / (float)k;
    }
}

// ---------------- launch ----------------
extern "C" void kernel_launch(void* const* d_in, const int* in_sizes, int n_in,
                              void* d_out, int out_size) {
    const float* avf = (const float*)d_in[0];
    const int*   seq = (const int*)  d_in[1];
    const float* W1  = (const float*)d_in[2];
    const float* b1  = (const float*)d_in[3];
    const float* W2  = (const float*)d_in[4];
    const float* b2  = (const float*)d_in[5];
    const float* W3  = (const float*)d_in[6];
    const float* b3  = (const float*)d_in[7];
    float* out = (float*)d_out;

    cudaFuncSetAttribute(fused_mlp_kernel,
                         cudaFuncAttributeMaxDynamicSharedMemorySize, SMEM_BYTES);

    prep_weff_kernel<<<1, H1_>>>(W2, b2, W3, b3);
    prep_w1t_kernel<<<(H1_ * D_) / 256, 256>>>(W1);

    dim3 grid(T_ / 64, B_);
    fused_mlp_kernel<<<grid, 256, SMEM_BYTES>>>(avf, seq, b1);

    topk_kernel<<<B_, 256>>>(seq, out);
}